// round 3
// baseline (speedup 1.0000x reference)
#include <cuda_runtime.h>
#include <math.h>

#define NN 8192
#define DD 32
#define HH 128
#define MMQ 8
#define TPB 512
#define NBLK 128
#define SPW 4
#define P36 36
#define P132 132
#define NSTEPS 10

// ---------------- device state ----------------
__device__ float g_yz[NN * DD];
__device__ float g_ylp[NN];
__device__ float g_y1z[NN * DD];
__device__ float g_y1lp[NN];
__device__ float g_kz[7][NN * DD];
__device__ float g_klp[7][NN];
__device__ float g_IPT[DD * DD];    // IPT[j*32+k] = IP[k][j]
__device__ float g_MmatT[HH * HH];  // MmatT[j*128+i] = W2[j,i]*B[i,j]
__device__ float g_trP;
__device__ float g_t, g_dt, g_dtc, g_t1;
__device__ int g_done, g_accept;
__device__ float g_partial[256];

// ---------------- prep: projection + M matrix ----------------
__global__ void prep_kernel(const float* __restrict__ G, const float* __restrict__ W1,
                            const float* __restrict__ W2, const float* __restrict__ W3,
                            const float* __restrict__ T) {
    __shared__ double Ad[MMQ][MMQ];
    __shared__ double Ainv[MMQ][MMQ];
    __shared__ float sAinvG[MMQ][DD];
    __shared__ float sP[DD][DD];
    __shared__ float sC[DD][HH];
    int tid = threadIdx.x;

    if (tid < MMQ * MMQ) {
        int i = tid >> 3, j = tid & 7;
        double s = 0.0;
        for (int d = 0; d < DD; d++) s += (double)G[i * DD + d] * (double)G[j * DD + d];
        Ad[i][j] = s;
    }
    __syncthreads();
    if (tid == 0) {
        double Mx[MMQ][2 * MMQ];
        for (int i = 0; i < MMQ; i++)
            for (int j = 0; j < MMQ; j++) {
                Mx[i][j] = Ad[i][j];
                Mx[i][MMQ + j] = (i == j) ? 1.0 : 0.0;
            }
        for (int col = 0; col < MMQ; col++) {
            int piv = col;
            double best = fabs(Mx[col][col]);
            for (int r = col + 1; r < MMQ; r++) {
                double v = fabs(Mx[r][col]);
                if (v > best) { best = v; piv = r; }
            }
            if (piv != col)
                for (int j = 0; j < 2 * MMQ; j++) {
                    double tmp = Mx[col][j]; Mx[col][j] = Mx[piv][j]; Mx[piv][j] = tmp;
                }
            double inv = 1.0 / Mx[col][col];
            for (int j = 0; j < 2 * MMQ; j++) Mx[col][j] *= inv;
            for (int r = 0; r < MMQ; r++)
                if (r != col) {
                    double fv = Mx[r][col];
                    for (int j = 0; j < 2 * MMQ; j++) Mx[r][j] -= fv * Mx[col][j];
                }
        }
        for (int i = 0; i < MMQ; i++)
            for (int j = 0; j < MMQ; j++) Ainv[i][j] = Mx[i][MMQ + j];
    }
    __syncthreads();
    if (tid < MMQ * DD) {
        int m = tid >> 5, d = tid & 31;
        double s = 0.0;
        for (int k = 0; k < MMQ; k++) s += Ainv[m][k] * (double)G[k * DD + d];
        sAinvG[m][d] = (float)s;
    }
    __syncthreads();
    for (int e = tid; e < DD * DD; e += blockDim.x) {
        int a = e >> 5, b = e & 31;
        float s = 0.f;
        for (int m = 0; m < MMQ; m++) s += G[m * DD + a] * sAinvG[m][b];
        sP[a][b] = s;
        g_IPT[b * DD + a] = ((a == b) ? 1.0f : 0.0f) - s;  // IP[a][b] stored transposed
    }
    __syncthreads();
    if (tid == 0) {
        float tr = 0.f;
        for (int a = 0; a < DD; a++) tr += sP[a][a];
        g_trP = tr;
        g_t = 0.f;
        g_dt = 0.25f;
        g_t1 = 2.0f * T[0];
    }
    // C = IP @ W3  (32 x 128)
    for (int e = tid; e < DD * HH; e += blockDim.x) {
        int a = e >> 7, j = e & 127;
        float s = 0.f;
        for (int b = 0; b < DD; b++)
            s += (((a == b) ? 1.0f : 0.0f) - sP[a][b]) * W3[b * HH + j];
        sC[a][j] = s;
    }
    __syncthreads();
    // MmatT[j][i] = W2[j,i] * B[i,j],  B = W1 @ C
    for (int e = tid; e < HH * HH; e += blockDim.x) {
        int j = e >> 7, i = e & 127;
        float s = 0.f;
        for (int a = 0; a < DD; a++) s += W1[i * DD + a] * sC[a][j];
        g_MmatT[j * HH + i] = s * W2[j * HH + i];
    }
}

// ---------------- init ----------------
__global__ void init_kernel(const float* __restrict__ z) {
    int total = NN * DD + NN;
    for (int i = blockIdx.x * blockDim.x + threadIdx.x; i < total; i += gridDim.x * blockDim.x) {
        if (i < NN * DD) g_yz[i] = z[i];
        else g_ylp[i - NN * DD] = 0.f;
    }
}

// ---------------- begin step ----------------
__global__ void begin_kernel() {
    float t = g_t, dt = g_dt, t1 = g_t1;
    int done = (t >= t1 - 1e-9f) ? 1 : 0;
    g_done = done;
    g_dtc = done ? 0.001f : fminf(dt, t1 - t);
}

// ---------------- the f(y) stage kernel ----------------
struct Coefs {
    float a0, a1, a2, a3, a4;
    int nk;
    int stage;
    int base_sel;
};

__global__ __launch_bounds__(TPB, 1) void stage_kernel(
    const float* __restrict__ W1, const float* __restrict__ b1,
    const float* __restrict__ W2, const float* __restrict__ b2,
    const float* __restrict__ W3, const float* __restrict__ b3, Coefs cf) {
    extern __shared__ float sm[];
    float* sW1 = sm;                        // HH*P36
    float* sW2 = sW1 + HH * P36;            // HH*P132
    float* sMT = sW2 + HH * P132;           // HH*P132
    float* sW3 = sMT + HH * P132;           // DD*P132
    float* sIPT = sW3 + DD * P132;          // DD*P36
    float* sb1 = sIPT + DD * P36;           // HH
    float* sb2 = sb1 + HH;                  // HH
    float* sb3 = sb2 + HH;                  // DD
    float* xs = sb3 + DD;                   // 16*SPW*DD
    float* hs = xs + 16 * SPW * DD;         // 16*SPW*HH

    int tid = threadIdx.x;
    for (int e = tid; e < HH * DD; e += TPB) sW1[(e >> 5) * P36 + (e & 31)] = W1[e];
    for (int e = tid; e < HH * HH; e += TPB) sW2[(e >> 7) * P132 + (e & 127)] = W2[e];
    for (int e = tid; e < HH * HH; e += TPB) sMT[(e >> 7) * P132 + (e & 127)] = g_MmatT[e];
    for (int e = tid; e < DD * HH; e += TPB) sW3[(e >> 7) * P132 + (e & 127)] = W3[e];
    for (int e = tid; e < DD * DD; e += TPB) sIPT[(e >> 5) * P36 + (e & 31)] = g_IPT[e];
    if (tid < HH) { sb1[tid] = b1[tid]; sb2[tid] = b2[tid]; }
    if (tid < DD) sb3[tid] = b3[tid];
    __syncthreads();

    int w = tid >> 5, lane = tid & 31;
    int n0 = (blockIdx.x * (TPB / 32) + w) * SPW;
    float dtc = g_dtc;
    const float* basez = cf.base_sel ? g_y1z : g_yz;
    float* xw = xs + w * (SPW * DD);
    float* hw = hs + w * (SPW * HH);

    // stage input x = base + dtc * sum(a_j * k_j)
    float xv[SPW];
#pragma unroll
    for (int s = 0; s < SPW; s++) {
        int n = n0 + s;
        float v = basez[n * DD + lane];
        if (cf.nk > 0) {
            float acc = cf.a0 * g_kz[0][n * DD + lane];
            if (cf.nk > 1) acc += cf.a1 * g_kz[1][n * DD + lane];
            if (cf.nk > 2) acc += cf.a2 * g_kz[2][n * DD + lane];
            if (cf.nk > 3) acc += cf.a3 * g_kz[3][n * DD + lane];
            if (cf.nk > 4) acc += cf.a4 * g_kz[4][n * DD + lane];
            v += dtc * acc;
        }
        xv[s] = v;
        xw[s * DD + lane] = v;
    }
    __syncwarp();

    // pass 1: h1pre = W1 @ x + b1 (lane owns j = c*32+lane)
    float h1[SPW][4];
#pragma unroll
    for (int s = 0; s < SPW; s++)
#pragma unroll
        for (int c = 0; c < 4; c++) h1[s][c] = sb1[c * 32 + lane];
#pragma unroll
    for (int d0 = 0; d0 < DD; d0 += 4) {
        float4 x4[SPW];
#pragma unroll
        for (int s = 0; s < SPW; s++) x4[s] = *(const float4*)&xw[s * DD + d0];
#pragma unroll
        for (int c = 0; c < 4; c++) {
            float4 wv = *(const float4*)&sW1[(c * 32 + lane) * P36 + d0];
#pragma unroll
            for (int s = 0; s < SPW; s++)
                h1[s][c] += wv.x * x4[s].x + wv.y * x4[s].y + wv.z * x4[s].z + wv.w * x4[s].w;
        }
    }
#pragma unroll
    for (int s = 0; s < SPW; s++)
#pragma unroll
        for (int c = 0; c < 4; c++) hw[s * HH + c * 32 + lane] = fmaxf(h1[s][c], 0.f);
    __syncwarp();

    // pass 2: h2pre = W2 @ relu(h1) + b2, and v[j] = sum_i MT[j][i]*d1[i]
    float h2[SPW][4], vv[SPW][4];
#pragma unroll
    for (int s = 0; s < SPW; s++)
#pragma unroll
        for (int c = 0; c < 4; c++) {
            h2[s][c] = sb2[c * 32 + lane];
            vv[s][c] = 0.f;
        }
    for (int i0 = 0; i0 < HH; i0 += 4) {
        float4 h4[SPW], m4[SPW];
#pragma unroll
        for (int s = 0; s < SPW; s++) {
            h4[s] = *(const float4*)&hw[s * HH + i0];
            m4[s].x = h4[s].x > 0.f ? 1.f : 0.f;
            m4[s].y = h4[s].y > 0.f ? 1.f : 0.f;
            m4[s].z = h4[s].z > 0.f ? 1.f : 0.f;
            m4[s].w = h4[s].w > 0.f ? 1.f : 0.f;
        }
#pragma unroll
        for (int c = 0; c < 4; c++) {
            int j = c * 32 + lane;
            float4 w2 = *(const float4*)&sW2[j * P132 + i0];
            float4 mm = *(const float4*)&sMT[j * P132 + i0];
#pragma unroll
            for (int s = 0; s < SPW; s++) {
                h2[s][c] += w2.x * h4[s].x + w2.y * h4[s].y + w2.z * h4[s].z + w2.w * h4[s].w;
                vv[s][c] += mm.x * m4[s].x + mm.y * m4[s].y + mm.z * m4[s].z + mm.w * m4[s].w;
            }
        }
    }
    __syncwarp();
    // relu(h2) back to staging; dlogp partial = sum_j d2[j]*v[j]
    float dlp[SPW];
#pragma unroll
    for (int s = 0; s < SPW; s++) {
        float acc = 0.f;
#pragma unroll
        for (int c = 0; c < 4; c++) {
            float h2v = h2[s][c];
            hw[s * HH + c * 32 + lane] = fmaxf(h2v, 0.f);
            if (h2v > 0.f) acc += vv[s][c];
        }
        dlp[s] = acc;
    }
    __syncwarp();

    // pass 3: dF = W3 @ relu(h2) + b3 (lane owns d = lane)
    float dF[SPW];
#pragma unroll
    for (int s = 0; s < SPW; s++) dF[s] = sb3[lane];
    for (int h0 = 0; h0 < HH; h0 += 4) {
        float4 w3 = *(const float4*)&sW3[lane * P132 + h0];
#pragma unroll
        for (int s = 0; s < SPW; s++) {
            float4 h24 = *(const float4*)&hw[s * HH + h0];
            dF[s] += w3.x * h24.x + w3.y * h24.y + w3.z * h24.z + w3.w * h24.w;
        }
    }
    __syncwarp();
    // t = x - dF -> staging (first 32 slots of hw row)
#pragma unroll
    for (int s = 0; s < SPW; s++) hw[s * HH + lane] = xv[s] - dF[s];
    __syncwarp();

    // pass 4: dz = (x - dF) @ IP - x
    float dz[SPW];
#pragma unroll
    for (int s = 0; s < SPW; s++) dz[s] = -xv[s];
#pragma unroll
    for (int k0 = 0; k0 < DD; k0 += 4) {
        float4 ip = *(const float4*)&sIPT[lane * P36 + k0];
#pragma unroll
        for (int s = 0; s < SPW; s++) {
            float4 t4 = *(const float4*)&hw[s * HH + k0];
            dz[s] += ip.x * t4.x + ip.y * t4.y + ip.z * t4.z + ip.w * t4.w;
        }
    }
    float trP = g_trP;
#pragma unroll
    for (int s = 0; s < SPW; s++) {
        int n = n0 + s;
        g_kz[cf.stage][n * DD + lane] = dz[s];
        float v = dlp[s];
#pragma unroll
        for (int off = 16; off > 0; off >>= 1) v += __shfl_xor_sync(0xffffffffu, v, off);
        if (lane == 0) g_klp[cf.stage][n] = v + trP;
    }
}

// ---------------- y1 combine ----------------
__global__ void combine_kernel() {
    const float c1 = (float)(35.0 / 384.0), c3 = (float)(500.0 / 1113.0),
                c4 = (float)(125.0 / 192.0), c5 = (float)(-2187.0 / 6784.0),
                c6 = (float)(11.0 / 84.0);
    float dtc = g_dtc;
    int total = NN * DD + NN;
    for (int i = blockIdx.x * blockDim.x + threadIdx.x; i < total; i += gridDim.x * blockDim.x) {
        if (i < NN * DD) {
            float s = c1 * g_kz[0][i] + c3 * g_kz[2][i] + c4 * g_kz[3][i] +
                      c5 * g_kz[4][i] + c6 * g_kz[5][i];
            g_y1z[i] = g_yz[i] + dtc * s;
        } else {
            int n = i - NN * DD;
            float s = c1 * g_klp[0][n] + c3 * g_klp[2][n] + c4 * g_klp[3][n] +
                      c5 * g_klp[4][n] + c6 * g_klp[5][n];
            g_y1lp[n] = g_ylp[n] + dtc * s;
        }
    }
}

// ---------------- error norm partials (deterministic) ----------------
__global__ void err_kernel() {
    const float e1 = (float)(35.0 / 384.0 - 5179.0 / 57600.0);
    const float e3 = (float)(500.0 / 1113.0 - 7571.0 / 16695.0);
    const float e4 = (float)(125.0 / 192.0 - 393.0 / 640.0);
    const float e5 = (float)(-2187.0 / 6784.0 + 92097.0 / 339200.0);
    const float e6 = (float)(11.0 / 84.0 - 187.0 / 2100.0);
    const float e7 = (float)(-1.0 / 40.0);
    float dtc = g_dtc;
    int total = NN * DD + NN;
    float acc = 0.f;
    for (int i = blockIdx.x * blockDim.x + threadIdx.x; i < total; i += gridDim.x * blockDim.x) {
        float ev, yv, y1v;
        if (i < NN * DD) {
            ev = dtc * (e1 * g_kz[0][i] + e3 * g_kz[2][i] + e4 * g_kz[3][i] +
                        e5 * g_kz[4][i] + e6 * g_kz[5][i] + e7 * g_kz[6][i]);
            yv = g_yz[i];
            y1v = g_y1z[i];
        } else {
            int n = i - NN * DD;
            ev = dtc * (e1 * g_klp[0][n] + e3 * g_klp[2][n] + e4 * g_klp[3][n] +
                        e5 * g_klp[4][n] + e6 * g_klp[5][n] + e7 * g_klp[6][n]);
            yv = g_ylp[n];
            y1v = g_y1lp[n];
        }
        float tol = 1e-5f + 1e-5f * fmaxf(fabsf(yv), fabsf(y1v));
        float r = ev / tol;
        acc += r * r;
    }
    __shared__ float red[256];
    red[threadIdx.x] = acc;
    __syncthreads();
    for (int s2 = 128; s2 > 0; s2 >>= 1) {
        if (threadIdx.x < s2) red[threadIdx.x] += red[threadIdx.x + s2];
        __syncthreads();
    }
    if (threadIdx.x == 0) g_partial[blockIdx.x] = red[0];
}

// ---------------- end step: controller update ----------------
__global__ void end_kernel() {
    __shared__ float red[256];
    red[threadIdx.x] = g_partial[threadIdx.x];
    __syncthreads();
    for (int s2 = 128; s2 > 0; s2 >>= 1) {
        if (threadIdx.x < s2) red[threadIdx.x] += red[threadIdx.x + s2];
        __syncthreads();
    }
    if (threadIdx.x == 0) {
        float errn = sqrtf(red[0] / (float)(NN * (DD + 1)));
        int done = g_done;
        float dtc = g_dtc;
        int accept = (!done) && (errn <= 1.0f);
        g_accept = accept;
        if (accept) g_t = g_t + dtc;
        float factor = (errn > 0.f) ? 0.9f * powf(errn, -0.2f) : 10.0f;
        factor = fminf(fmaxf(factor, 0.2f), 10.0f);
        if (!done) g_dt = fminf(fmaxf(dtc * factor, 1e-6f), g_t1);
    }
}

// ---------------- conditional accept ----------------
__global__ void select_kernel() {
    if (!g_accept) return;
    int total = NN * DD + NN;
    for (int i = blockIdx.x * blockDim.x + threadIdx.x; i < total; i += gridDim.x * blockDim.x) {
        if (i < NN * DD) g_yz[i] = g_y1z[i];
        else g_ylp[i - NN * DD] = g_y1lp[i - NN * DD];
    }
}

__global__ void final_kernel(float* __restrict__ out) {
    for (int i = blockIdx.x * blockDim.x + threadIdx.x; i < NN * DD; i += gridDim.x * blockDim.x)
        out[i] = g_yz[i];
}

// ---------------- launch ----------------
extern "C" void kernel_launch(void* const* d_in, const int* in_sizes, int n_in,
                              void* d_out, int out_size) {
    const float* z  = (const float*)d_in[0];
    const float* G  = (const float*)d_in[1];
    const float* W1 = (const float*)d_in[2];
    const float* b1 = (const float*)d_in[3];
    const float* W2 = (const float*)d_in[4];
    const float* b2 = (const float*)d_in[5];
    const float* W3 = (const float*)d_in[6];
    const float* b3 = (const float*)d_in[7];
    const float* T  = (const float*)d_in[8];

    const int smem_floats = HH * P36 + 2 * HH * P132 + DD * P132 + DD * P36 +
                            2 * HH + DD + 16 * SPW * DD + 16 * SPW * HH;
    const int smem_bytes = smem_floats * 4;
    cudaFuncSetAttribute(stage_kernel, cudaFuncAttributeMaxDynamicSharedMemorySize, smem_bytes);

    prep_kernel<<<1, 256>>>(G, W1, W2, W3, T);
    init_kernel<<<256, 256>>>(z);

    Coefs cfs[7];
    cfs[0] = {0.f, 0.f, 0.f, 0.f, 0.f, 0, 0, 0};
    cfs[1] = {0.2f, 0.f, 0.f, 0.f, 0.f, 1, 1, 0};
    cfs[2] = {(float)(3.0 / 40.0), (float)(9.0 / 40.0), 0.f, 0.f, 0.f, 2, 2, 0};
    cfs[3] = {(float)(44.0 / 45.0), (float)(-56.0 / 15.0), (float)(32.0 / 9.0), 0.f, 0.f, 3, 3, 0};
    cfs[4] = {(float)(19372.0 / 6561.0), (float)(-25360.0 / 2187.0), (float)(64448.0 / 6561.0),
              (float)(-212.0 / 729.0), 0.f, 4, 4, 0};
    cfs[5] = {(float)(9017.0 / 3168.0), (float)(-355.0 / 33.0), (float)(46732.0 / 5247.0),
              (float)(49.0 / 176.0), (float)(-5103.0 / 18656.0), 5, 5, 0};
    cfs[6] = {0.f, 0.f, 0.f, 0.f, 0.f, 0, 6, 1};

    for (int step = 0; step < NSTEPS; step++) {
        begin_kernel<<<1, 1>>>();
        for (int s = 0; s < 6; s++)
            stage_kernel<<<NBLK, TPB, smem_bytes>>>(W1, b1, W2, b2, W3, b3, cfs[s]);
        combine_kernel<<<256, 256>>>();
        stage_kernel<<<NBLK, TPB, smem_bytes>>>(W1, b1, W2, b2, W3, b3, cfs[6]);
        err_kernel<<<256, 256>>>();
        end_kernel<<<1, 256>>>();
        select_kernel<<<256, 256>>>();
    }
    final_kernel<<<256, 256>>>((float*)d_out);
}

// round 6
// speedup vs baseline: 1.0278x; 1.0278x over previous
#include <cuda_runtime.h>
#include <math.h>

#define NN 8192
#define DD 32
#define HH 128
#define MMQ 8
#define TPB 512
#define NBLK 128
#define SPW 4
#define P36 36
#define P132 132
#define NSTEPS 10

// ---------------- device state ----------------
__device__ float g_yz[NN * DD];
__device__ float g_ylp[NN];
__device__ float g_y1z[NN * DD];
__device__ float g_y1lp[NN];
__device__ float g_kz[7][NN * DD];
__device__ float g_klp[7][NN];
__device__ float g_IPT[DD * DD];    // IPT[j*32+k] = IP[k][j]
__device__ float g_MmatT[HH * HH];  // MmatT[j*128+i] = W2[j,i]*B[i,j]
__device__ float g_trP;
__device__ float g_t, g_dt, g_dtc, g_t1;
__device__ int g_done, g_accept;
__device__ float g_partial[256];

// ---------------- prep: projection + M matrix ----------------
__global__ void prep_kernel(const float* __restrict__ G, const float* __restrict__ W1,
                            const float* __restrict__ W2, const float* __restrict__ W3,
                            const float* __restrict__ T) {
    __shared__ double Ad[MMQ][MMQ];
    __shared__ double Ainv[MMQ][MMQ];
    __shared__ float sAinvG[MMQ][DD];
    __shared__ float sP[DD][DD];
    __shared__ float sC[DD][HH];
    int tid = threadIdx.x;

    if (tid < MMQ * MMQ) {
        int i = tid >> 3, j = tid & 7;
        double s = 0.0;
        for (int d = 0; d < DD; d++) s += (double)G[i * DD + d] * (double)G[j * DD + d];
        Ad[i][j] = s;
    }
    __syncthreads();
    if (tid == 0) {
        double Mx[MMQ][2 * MMQ];
        for (int i = 0; i < MMQ; i++)
            for (int j = 0; j < MMQ; j++) {
                Mx[i][j] = Ad[i][j];
                Mx[i][MMQ + j] = (i == j) ? 1.0 : 0.0;
            }
        for (int col = 0; col < MMQ; col++) {
            int piv = col;
            double best = fabs(Mx[col][col]);
            for (int r = col + 1; r < MMQ; r++) {
                double v = fabs(Mx[r][col]);
                if (v > best) { best = v; piv = r; }
            }
            if (piv != col)
                for (int j = 0; j < 2 * MMQ; j++) {
                    double tmp = Mx[col][j]; Mx[col][j] = Mx[piv][j]; Mx[piv][j] = tmp;
                }
            double inv = 1.0 / Mx[col][col];
            for (int j = 0; j < 2 * MMQ; j++) Mx[col][j] *= inv;
            for (int r = 0; r < MMQ; r++)
                if (r != col) {
                    double fv = Mx[r][col];
                    for (int j = 0; j < 2 * MMQ; j++) Mx[r][j] -= fv * Mx[col][j];
                }
        }
        for (int i = 0; i < MMQ; i++)
            for (int j = 0; j < MMQ; j++) Ainv[i][j] = Mx[i][MMQ + j];
    }
    __syncthreads();
    if (tid < MMQ * DD) {
        int m = tid >> 5, d = tid & 31;
        double s = 0.0;
        for (int k = 0; k < MMQ; k++) s += Ainv[m][k] * (double)G[k * DD + d];
        sAinvG[m][d] = (float)s;
    }
    __syncthreads();
    for (int e = tid; e < DD * DD; e += blockDim.x) {
        int a = e >> 5, b = e & 31;
        float s = 0.f;
        for (int m = 0; m < MMQ; m++) s += G[m * DD + a] * sAinvG[m][b];
        sP[a][b] = s;
        g_IPT[b * DD + a] = ((a == b) ? 1.0f : 0.0f) - s;  // IP[a][b] stored transposed
    }
    __syncthreads();
    if (tid == 0) {
        float tr = 0.f;
        for (int a = 0; a < DD; a++) tr += sP[a][a];
        g_trP = tr;
        float t1 = 2.0f * T[0];
        g_t = 0.f;
        g_dt = 0.25f;
        g_t1 = t1;
        int done = (0.f >= t1 - 1e-9f) ? 1 : 0;
        g_done = done;
        g_dtc = done ? 0.001f : fminf(0.25f, t1);
    }
    // C = IP @ W3  (32 x 128)
    for (int e = tid; e < DD * HH; e += blockDim.x) {
        int a = e >> 7, j = e & 127;
        float s = 0.f;
        for (int b = 0; b < DD; b++)
            s += (((a == b) ? 1.0f : 0.0f) - sP[a][b]) * W3[b * HH + j];
        sC[a][j] = s;
    }
    __syncthreads();
    // MmatT[j][i] = W2[j,i] * B[i,j],  B = W1 @ C
    for (int e = tid; e < HH * HH; e += blockDim.x) {
        int j = e >> 7, i = e & 127;
        float s = 0.f;
        for (int a = 0; a < DD; a++) s += W1[i * DD + a] * sC[a][j];
        g_MmatT[j * HH + i] = s * W2[j * HH + i];
    }
}

// ---------------- init ----------------
__global__ void init_kernel(const float* __restrict__ z) {
    int total = NN * DD + NN;
    for (int i = blockIdx.x * blockDim.x + threadIdx.x; i < total; i += gridDim.x * blockDim.x) {
        if (i < NN * DD) g_yz[i] = z[i];
        else g_ylp[i - NN * DD] = 0.f;
    }
}

// ---------------- the f(y) stage kernel ----------------
struct Coefs {
    float a0, a1, a2, a3, a4;
    int nk;
    int stage;
    int base_sel;
};

__global__ __launch_bounds__(TPB, 1) void stage_kernel(
    const float* __restrict__ W1, const float* __restrict__ b1,
    const float* __restrict__ W2, const float* __restrict__ b2,
    const float* __restrict__ W3, const float* __restrict__ b3, Coefs cf) {
    extern __shared__ float sm[];
    float* sW1 = sm;                        // HH*P36
    float* sW2 = sW1 + HH * P36;            // HH*P132
    float* sMT = sW2 + HH * P132;           // HH*P132
    float* sW3 = sMT + HH * P132;           // DD*P132
    float* sIPT = sW3 + DD * P132;          // DD*P36
    float* sb1 = sIPT + DD * P36;           // HH
    float* sb2 = sb1 + HH;                  // HH
    float* sb3 = sb2 + HH;                  // DD
    float* xs = sb3 + DD;                   // 16*SPW*DD
    float* hs = xs + 16 * SPW * DD;         // 16*SPW*HH

    int tid = threadIdx.x;
    int w = tid >> 5, lane = tid & 31;
    int n0 = (blockIdx.x * (TPB / 32) + w) * SPW;
    float dtc = g_dtc;
    const float* basez = cf.base_sel ? g_y1z : g_yz;
    float* xw = xs + w * (SPW * DD);
    float* hw = hs + w * (SPW * HH);

    // ---- stage input x = base + dtc * sum(a_j * k_j): issue these global
    // loads FIRST so their L2 latency hides under the weight staging below.
    float xv[SPW];
#pragma unroll
    for (int s = 0; s < SPW; s++) {
        int n = n0 + s;
        float v = basez[n * DD + lane];
        if (cf.nk > 0) {
            float acc = cf.a0 * g_kz[0][n * DD + lane];
            if (cf.nk > 1) acc += cf.a1 * g_kz[1][n * DD + lane];
            if (cf.nk > 2) acc += cf.a2 * g_kz[2][n * DD + lane];
            if (cf.nk > 3) acc += cf.a3 * g_kz[3][n * DD + lane];
            if (cf.nk > 4) acc += cf.a4 * g_kz[4][n * DD + lane];
            v += dtc * acc;
        }
        xv[s] = v;
        xw[s * DD + lane] = v;
    }

    // ---- weight staging
    for (int e = tid; e < HH * DD; e += TPB) sW1[(e >> 5) * P36 + (e & 31)] = W1[e];
    for (int e = tid; e < HH * HH; e += TPB) sW2[(e >> 7) * P132 + (e & 127)] = W2[e];
    for (int e = tid; e < HH * HH; e += TPB) sMT[(e >> 7) * P132 + (e & 127)] = g_MmatT[e];
    for (int e = tid; e < DD * HH; e += TPB) sW3[(e >> 7) * P132 + (e & 127)] = W3[e];
    for (int e = tid; e < DD * DD; e += TPB) sIPT[(e >> 5) * P36 + (e & 31)] = g_IPT[e];
    if (tid < HH) { sb1[tid] = b1[tid]; sb2[tid] = b2[tid]; }
    if (tid < DD) sb3[tid] = b3[tid];
    __syncthreads();

    // pass 1: h1pre = W1 @ x + b1 (lane owns j = c*32+lane)
    float h1[SPW][4];
#pragma unroll
    for (int s = 0; s < SPW; s++)
#pragma unroll
        for (int c = 0; c < 4; c++) h1[s][c] = sb1[c * 32 + lane];
#pragma unroll
    for (int d0 = 0; d0 < DD; d0 += 4) {
        float4 x4[SPW];
#pragma unroll
        for (int s = 0; s < SPW; s++) x4[s] = *(const float4*)&xw[s * DD + d0];
#pragma unroll
        for (int c = 0; c < 4; c++) {
            float4 wv = *(const float4*)&sW1[(c * 32 + lane) * P36 + d0];
#pragma unroll
            for (int s = 0; s < SPW; s++)
                h1[s][c] += wv.x * x4[s].x + wv.y * x4[s].y + wv.z * x4[s].z + wv.w * x4[s].w;
        }
    }
#pragma unroll
    for (int s = 0; s < SPW; s++)
#pragma unroll
        for (int c = 0; c < 4; c++) hw[s * HH + c * 32 + lane] = fmaxf(h1[s][c], 0.f);
    __syncwarp();

    // pass 2 (software pipelined): h2pre = W2 @ relu(h1) + b2,
    // and v[j] = sum_i MT[j][i]*mask(h1[i])
    float h2[SPW][4], vv[SPW][4];
#pragma unroll
    for (int s = 0; s < SPW; s++)
#pragma unroll
        for (int c = 0; c < 4; c++) {
            h2[s][c] = sb2[c * 32 + lane];
            vv[s][c] = 0.f;
        }
    {
        const float* w2base = sW2 + lane * P132;
        const float* mtbase = sMT + lane * P132;
        // prime the pipeline
        float4 h4n[SPW];
#pragma unroll
        for (int s = 0; s < SPW; s++) h4n[s] = *(const float4*)&hw[s * HH + 0];
        float4 w2n = *(const float4*)&w2base[0];
        float4 mmn = *(const float4*)&mtbase[0];
#pragma unroll 8
        for (int i0 = 0; i0 < HH; i0 += 4) {
            float4 h4[SPW], m4[SPW];
#pragma unroll
            for (int s = 0; s < SPW; s++) {
                h4[s] = h4n[s];
                m4[s].x = h4[s].x > 0.f ? 1.f : 0.f;
                m4[s].y = h4[s].y > 0.f ? 1.f : 0.f;
                m4[s].z = h4[s].z > 0.f ? 1.f : 0.f;
                m4[s].w = h4[s].w > 0.f ? 1.f : 0.f;
            }
            // prefetch activations for next i0
            if (i0 + 4 < HH) {
#pragma unroll
                for (int s = 0; s < SPW; s++) h4n[s] = *(const float4*)&hw[s * HH + i0 + 4];
            }
#pragma unroll
            for (int c = 0; c < 4; c++) {
                float4 w2 = w2n, mm = mmn;
                // prefetch weights for next (c, i0)
                int cn = (c < 3) ? (c + 1) : 0;
                int i0n = (c < 3) ? i0 : (i0 + 4);
                if (i0n < HH) {
                    w2n = *(const float4*)&w2base[cn * 32 * P132 + i0n];
                    mmn = *(const float4*)&mtbase[cn * 32 * P132 + i0n];
                }
#pragma unroll
                for (int s = 0; s < SPW; s++) {
                    h2[s][c] += w2.x * h4[s].x + w2.y * h4[s].y + w2.z * h4[s].z + w2.w * h4[s].w;
                    vv[s][c] += mm.x * m4[s].x + mm.y * m4[s].y + mm.z * m4[s].z + mm.w * m4[s].w;
                }
            }
        }
    }
    __syncwarp();
    // relu(h2) back to staging; dlogp partial = sum_j d2[j]*v[j]
    float dlp[SPW];
#pragma unroll
    for (int s = 0; s < SPW; s++) {
        float acc = 0.f;
#pragma unroll
        for (int c = 0; c < 4; c++) {
            float h2v = h2[s][c];
            hw[s * HH + c * 32 + lane] = fmaxf(h2v, 0.f);
            if (h2v > 0.f) acc += vv[s][c];
        }
        dlp[s] = acc;
    }
    __syncwarp();

    // pass 3 (software pipelined): dF = W3 @ relu(h2) + b3 (lane owns d = lane)
    float dF[SPW];
#pragma unroll
    for (int s = 0; s < SPW; s++) dF[s] = sb3[lane];
    {
        const float* w3base = sW3 + lane * P132;
        float4 w3n = *(const float4*)&w3base[0];
        float4 h24n[SPW];
#pragma unroll
        for (int s = 0; s < SPW; s++) h24n[s] = *(const float4*)&hw[s * HH + 0];
#pragma unroll 8
        for (int h0 = 0; h0 < HH; h0 += 4) {
            float4 w3 = w3n;
            float4 h24[SPW];
#pragma unroll
            for (int s = 0; s < SPW; s++) h24[s] = h24n[s];
            if (h0 + 4 < HH) {
                w3n = *(const float4*)&w3base[h0 + 4];
#pragma unroll
                for (int s = 0; s < SPW; s++) h24n[s] = *(const float4*)&hw[s * HH + h0 + 4];
            }
#pragma unroll
            for (int s = 0; s < SPW; s++)
                dF[s] += w3.x * h24[s].x + w3.y * h24[s].y + w3.z * h24[s].z + w3.w * h24[s].w;
        }
    }
    __syncwarp();
    // t = x - dF -> staging (first 32 slots of hw row)
#pragma unroll
    for (int s = 0; s < SPW; s++) hw[s * HH + lane] = xv[s] - dF[s];
    __syncwarp();

    // pass 4: dz = (x - dF) @ IP - x
    float dz[SPW];
#pragma unroll
    for (int s = 0; s < SPW; s++) dz[s] = -xv[s];
#pragma unroll
    for (int k0 = 0; k0 < DD; k0 += 4) {
        float4 ip = *(const float4*)&sIPT[lane * P36 + k0];
#pragma unroll
        for (int s = 0; s < SPW; s++) {
            float4 t4 = *(const float4*)&hw[s * HH + k0];
            dz[s] += ip.x * t4.x + ip.y * t4.y + ip.z * t4.z + ip.w * t4.w;
        }
    }
    float trP = g_trP;
#pragma unroll
    for (int s = 0; s < SPW; s++) {
        int n = n0 + s;
        g_kz[cf.stage][n * DD + lane] = dz[s];
        float v = dlp[s];
#pragma unroll
        for (int off = 16; off > 0; off >>= 1) v += __shfl_xor_sync(0xffffffffu, v, off);
        if (lane == 0) g_klp[cf.stage][n] = v + trP;
    }
}

// ---------------- y1 combine ----------------
__global__ void combine_kernel() {
    const float c1 = (float)(35.0 / 384.0), c3 = (float)(500.0 / 1113.0),
                c4 = (float)(125.0 / 192.0), c5 = (float)(-2187.0 / 6784.0),
                c6 = (float)(11.0 / 84.0);
    float dtc = g_dtc;
    int total = NN * DD + NN;
    for (int i = blockIdx.x * blockDim.x + threadIdx.x; i < total; i += gridDim.x * blockDim.x) {
        if (i < NN * DD) {
            float s = c1 * g_kz[0][i] + c3 * g_kz[2][i] + c4 * g_kz[3][i] +
                      c5 * g_kz[4][i] + c6 * g_kz[5][i];
            g_y1z[i] = g_yz[i] + dtc * s;
        } else {
            int n = i - NN * DD;
            float s = c1 * g_klp[0][n] + c3 * g_klp[2][n] + c4 * g_klp[3][n] +
                      c5 * g_klp[4][n] + c6 * g_klp[5][n];
            g_y1lp[n] = g_ylp[n] + dtc * s;
        }
    }
}

// ---------------- error norm partials (deterministic) ----------------
__global__ void err_kernel() {
    const float e1 = (float)(35.0 / 384.0 - 5179.0 / 57600.0);
    const float e3 = (float)(500.0 / 1113.0 - 7571.0 / 16695.0);
    const float e4 = (float)(125.0 / 192.0 - 393.0 / 640.0);
    const float e5 = (float)(-2187.0 / 6784.0 + 92097.0 / 339200.0);
    const float e6 = (float)(11.0 / 84.0 - 187.0 / 2100.0);
    const float e7 = (float)(-1.0 / 40.0);
    float dtc = g_dtc;
    int total = NN * DD + NN;
    float acc = 0.f;
    for (int i = blockIdx.x * blockDim.x + threadIdx.x; i < total; i += gridDim.x * blockDim.x) {
        float ev, yv, y1v;
        if (i < NN * DD) {
            ev = dtc * (e1 * g_kz[0][i] + e3 * g_kz[2][i] + e4 * g_kz[3][i] +
                        e5 * g_kz[4][i] + e6 * g_kz[5][i] + e7 * g_kz[6][i]);
            yv = g_yz[i];
            y1v = g_y1z[i];
        } else {
            int n = i - NN * DD;
            ev = dtc * (e1 * g_klp[0][n] + e3 * g_klp[2][n] + e4 * g_klp[3][n] +
                        e5 * g_klp[4][n] + e6 * g_klp[5][n] + e7 * g_klp[6][n]);
            yv = g_ylp[n];
            y1v = g_y1lp[n];
        }
        float tol = 1e-5f + 1e-5f * fmaxf(fabsf(yv), fabsf(y1v));
        float r = ev / tol;
        acc += r * r;
    }
    __shared__ float red[256];
    red[threadIdx.x] = acc;
    __syncthreads();
    for (int s2 = 128; s2 > 0; s2 >>= 1) {
        if (threadIdx.x < s2) red[threadIdx.x] += red[threadIdx.x + s2];
        __syncthreads();
    }
    if (threadIdx.x == 0) g_partial[blockIdx.x] = red[0];
}

// ---------------- end step: controller update + next-step begin ----------------
__global__ void end_kernel() {
    __shared__ float red[256];
    red[threadIdx.x] = g_partial[threadIdx.x];
    __syncthreads();
    for (int s2 = 128; s2 > 0; s2 >>= 1) {
        if (threadIdx.x < s2) red[threadIdx.x] += red[threadIdx.x + s2];
        __syncthreads();
    }
    if (threadIdx.x == 0) {
        float errn = sqrtf(red[0] / (float)(NN * (DD + 1)));
        int done = g_done;
        float dtc = g_dtc;
        float t1 = g_t1;
        int accept = (!done) && (errn <= 1.0f);
        g_accept = accept;
        float t = g_t;
        if (accept) t += dtc;
        g_t = t;
        float factor = (errn > 0.f) ? 0.9f * powf(errn, -0.2f) : 10.0f;
        factor = fminf(fmaxf(factor, 0.2f), 10.0f);
        float dt = g_dt;
        if (!done) dt = fminf(fmaxf(dtc * factor, 1e-6f), t1);
        g_dt = dt;
        // fused "begin" for the next step
        int done2 = (t >= t1 - 1e-9f) ? 1 : 0;
        g_done = done2;
        g_dtc = done2 ? 0.001f : fminf(dt, t1 - t);
    }
}

// ---------------- conditional accept ----------------
__global__ void select_kernel() {
    if (!g_accept) return;
    int total = NN * DD + NN;
    for (int i = blockIdx.x * blockDim.x + threadIdx.x; i < total; i += gridDim.x * blockDim.x) {
        if (i < NN * DD) g_yz[i] = g_y1z[i];
        else g_ylp[i - NN * DD] = g_y1lp[i - NN * DD];
    }
}

__global__ void final_kernel(float* __restrict__ out) {
    for (int i = blockIdx.x * blockDim.x + threadIdx.x; i < NN * DD; i += gridDim.x * blockDim.x)
        out[i] = g_yz[i];
}

// ---------------- launch ----------------
extern "C" void kernel_launch(void* const* d_in, const int* in_sizes, int n_in,
                              void* d_out, int out_size) {
    const float* z  = (const float*)d_in[0];
    const float* G  = (const float*)d_in[1];
    const float* W1 = (const float*)d_in[2];
    const float* b1 = (const float*)d_in[3];
    const float* W2 = (const float*)d_in[4];
    const float* b2 = (const float*)d_in[5];
    const float* W3 = (const float*)d_in[6];
    const float* b3 = (const float*)d_in[7];
    const float* T  = (const float*)d_in[8];

    const int smem_floats = HH * P36 + 2 * HH * P132 + DD * P132 + DD * P36 +
                            2 * HH + DD + 16 * SPW * DD + 16 * SPW * HH;
    const int smem_bytes = smem_floats * 4;
    cudaFuncSetAttribute(stage_kernel, cudaFuncAttributeMaxDynamicSharedMemorySize, smem_bytes);

    prep_kernel<<<1, 256>>>(G, W1, W2, W3, T);
    init_kernel<<<256, 256>>>(z);

    Coefs cfs[7];
    cfs[0] = {0.f, 0.f, 0.f, 0.f, 0.f, 0, 0, 0};
    cfs[1] = {0.2f, 0.f, 0.f, 0.f, 0.f, 1, 1, 0};
    cfs[2] = {(float)(3.0 / 40.0), (float)(9.0 / 40.0), 0.f, 0.f, 0.f, 2, 2, 0};
    cfs[3] = {(float)(44.0 / 45.0), (float)(-56.0 / 15.0), (float)(32.0 / 9.0), 0.f, 0.f, 3, 3, 0};
    cfs[4] = {(float)(19372.0 / 6561.0), (float)(-25360.0 / 2187.0), (float)(64448.0 / 6561.0),
              (float)(-212.0 / 729.0), 0.f, 4, 4, 0};
    cfs[5] = {(float)(9017.0 / 3168.0), (float)(-355.0 / 33.0), (float)(46732.0 / 5247.0),
              (float)(49.0 / 176.0), (float)(-5103.0 / 18656.0), 5, 5, 0};
    cfs[6] = {0.f, 0.f, 0.f, 0.f, 0.f, 0, 6, 1};

    for (int step = 0; step < NSTEPS; step++) {
        for (int s = 0; s < 6; s++)
            stage_kernel<<<NBLK, TPB, smem_bytes>>>(W1, b1, W2, b2, W3, b3, cfs[s]);
        combine_kernel<<<256, 256>>>();
        stage_kernel<<<NBLK, TPB, smem_bytes>>>(W1, b1, W2, b2, W3, b3, cfs[6]);
        err_kernel<<<256, 256>>>();
        end_kernel<<<1, 256>>>();
        select_kernel<<<256, 256>>>();
    }
    final_kernel<<<256, 256>>>((float*)d_out);
}